// round 12
// baseline (speedup 1.0000x reference)
#include <cuda_runtime.h>
#include <cstdint>

#define NN 100000
#define EE 1600000

// ---- device scratch ----
__device__ int   g_cnt[NN];       // zero-init by CUDA; re-zeroed each call in scan_local
__device__ int   g_off[NN + 1];
__device__ int   g_cur[NN];
__device__ int   g_bsum[1024];
__device__ int   g_csr[EE];
__device__ float g_dinv[NN];
__device__ float g_G[NN * 128];
__device__ float g_X2[NN * 128];

// ------------------------------------------------------------------
// CSR build
// ------------------------------------------------------------------
__global__ void count_kernel(const int* __restrict__ dst, int e) {
    int i = blockIdx.x * blockDim.x + threadIdx.x;
    if (i < e) atomicAdd(&g_cnt[dst[i]], 1);
}
// local exclusive scan (1024/block) + dinv + re-zero counts
__global__ __launch_bounds__(256) void scan_local_kernel(int n) {
    __shared__ int ssum[256];
    int t = threadIdx.x;
    int base = blockIdx.x * 1024 + t * 4;
    int c0 = (base + 0 < n) ? g_cnt[base + 0] : 0;
    int c1 = (base + 1 < n) ? g_cnt[base + 1] : 0;
    int c2 = (base + 2 < n) ? g_cnt[base + 2] : 0;
    int c3 = (base + 3 < n) ? g_cnt[base + 3] : 0;
    if (base + 0 < n) { g_dinv[base + 0] = rsqrtf((float)c0 + 1.0f); g_cnt[base + 0] = 0; }
    if (base + 1 < n) { g_dinv[base + 1] = rsqrtf((float)c1 + 1.0f); g_cnt[base + 1] = 0; }
    if (base + 2 < n) { g_dinv[base + 2] = rsqrtf((float)c2 + 1.0f); g_cnt[base + 2] = 0; }
    if (base + 3 < n) { g_dinv[base + 3] = rsqrtf((float)c3 + 1.0f); g_cnt[base + 3] = 0; }
    int tsum = c0 + c1 + c2 + c3;
    ssum[t] = tsum;
    __syncthreads();
    for (int off = 1; off < 256; off <<= 1) {
        int v = (t >= off) ? ssum[t - off] : 0;
        __syncthreads();
        ssum[t] += v;
        __syncthreads();
    }
    int excl = ssum[t] - tsum;
    if (base + 0 < n) g_off[base + 0] = excl;
    if (base + 1 < n) g_off[base + 1] = excl + c0;
    if (base + 2 < n) g_off[base + 2] = excl + c0 + c1;
    if (base + 3 < n) g_off[base + 3] = excl + c0 + c1 + c2;
    if (t == 255) g_bsum[blockIdx.x] = ssum[255];
}
__global__ __launch_bounds__(1024) void scan_bsums_kernel(int nb) {
    __shared__ int s[1024];
    int t = threadIdx.x;
    int v = (t < nb) ? g_bsum[t] : 0;
    s[t] = v;
    __syncthreads();
    for (int off = 1; off < 1024; off <<= 1) {
        int u = (t >= off) ? s[t - off] : 0;
        __syncthreads();
        s[t] += u;
        __syncthreads();
    }
    if (t < nb) g_bsum[t] = s[t] - v;
}
__global__ void scan_add_kernel(int n, int e) {
    int i = blockIdx.x * blockDim.x + threadIdx.x;
    if (i < n) {
        int v = g_off[i] + g_bsum[i >> 10];
        g_off[i] = v;
        g_cur[i] = v;
    }
    if (i == 0) g_off[n] = e;
}
__global__ void scatter_kernel(const int* __restrict__ src,
                               const int* __restrict__ dst, int e) {
    int i = blockIdx.x * blockDim.x + threadIdx.x;
    if (i < e) {
        int pos = atomicAdd(&g_cur[dst[i]], 1);
        g_csr[pos] = src[i];
    }
}

// ------------------------------------------------------------------
// tf32 mma.sync GEMM (sm_80-compatible PTX; runs on tensor pipe)
// R9-proven mainloop: scalar LDS fragments, natural k order.
// ------------------------------------------------------------------
__device__ __forceinline__ uint32_t cvt_tf32(float x) {
    uint32_t r;
    asm("cvt.rna.tf32.f32 %0, %1;" : "=r"(r) : "f"(x));
    return r;
}
__device__ __forceinline__ void mma8(float* d, const uint32_t* a, const uint32_t* b) {
    asm volatile(
        "mma.sync.aligned.m16n8k8.row.col.f32.tf32.tf32.f32 "
        "{%0,%1,%2,%3}, {%4,%5,%6,%7}, {%8,%9}, {%0,%1,%2,%3};"
        : "+f"(d[0]), "+f"(d[1]), "+f"(d[2]), "+f"(d[3])
        : "r"(a[0]), "r"(a[1]), "r"(a[2]), "r"(a[3]), "r"(b[0]), "r"(b[1]));
}

// smem (floats): Bhi[128*132], Blo[128*132], Ahi[128*68], Alo[128*68]
#define OFF_BHI 0
#define OFF_BLO 16896
#define OFF_AHI 33792
#define OFF_ALO 42496
#define GEMM_SMEM_FL 51200
#define GEMM_SMEM_B (GEMM_SMEM_FL * 4)

// load one A chunk (K=64 cols starting at c*64) into 8 float4 regs
__device__ __forceinline__ void load_A_regs(
    const float* __restrict__ X, int trow, int c, int n, int tid, float4* va)
{
#pragma unroll
    for (int j = 0; j < 8; j++) {
        int i4 = tid + j * 256;
        int m = i4 >> 4, q = i4 & 15;
        int row = trow + m;
        va[j] = make_float4(0.f, 0.f, 0.f, 0.f);
        if (row < n)
            va[j] = *(const float4*)(X + (size_t)row * 128 + c * 64 + q * 4);
    }
}

// convert regs -> tf32 hi/lo and store to smem A buffers (stride 68)
__device__ __forceinline__ void store_A_smem(float* sm, int tid, const float4* va)
{
#pragma unroll
    for (int j = 0; j < 8; j++) {
        int i4 = tid + j * 256;
        int m = i4 >> 4, q = i4 & 15;
        float4 v = va[j];
        uint32_t h0 = cvt_tf32(v.x), h1 = cvt_tf32(v.y);
        uint32_t h2 = cvt_tf32(v.z), h3 = cvt_tf32(v.w);
        uint32_t l0 = cvt_tf32(v.x - __uint_as_float(h0));
        uint32_t l1 = cvt_tf32(v.y - __uint_as_float(h1));
        uint32_t l2 = cvt_tf32(v.z - __uint_as_float(h2));
        uint32_t l3 = cvt_tf32(v.w - __uint_as_float(h3));
        float* ah = sm + OFF_AHI + m * 68 + q * 4;
        float* al = sm + OFF_ALO + m * 68 + q * 4;
        ah[0] = __uint_as_float(h0); ah[1] = __uint_as_float(h1);
        ah[2] = __uint_as_float(h2); ah[3] = __uint_as_float(h3);
        al[0] = __uint_as_float(l0); al[1] = __uint_as_float(l1);
        al[2] = __uint_as_float(l2); al[3] = __uint_as_float(l3);
    }
}

// G = (X @ W) * dinv[row]; persistent; M-tile 128, N=128, K=128 (2 chunks of 64)
__global__ __launch_bounds__(256) void gemm_mma_kernel(
    const float* __restrict__ Xext, const float* __restrict__ W,
    int n, int use_x2)
{
    extern __shared__ float sm[];
    const float* X = use_x2 ? g_X2 : Xext;
    int tid = threadIdx.x, w = tid >> 5, lane = tid & 31;
    int g = lane >> 2, t4 = lane & 3;

    // fill W hi/lo once: Bs[n][k] = W[k][n], stride 132
    for (int i = tid; i < 128 * 128; i += 256) {
        int k = i >> 7, nn2 = i & 127;
        float wv = W[i];
        uint32_t hi = cvt_tf32(wv);
        uint32_t lo = cvt_tf32(wv - __uint_as_float(hi));
        sm[OFF_BHI + nn2 * 132 + k] = __uint_as_float(hi);
        sm[OFF_BLO + nn2 * 132 + k] = __uint_as_float(lo);
    }

    int rb = (w >> 1) * 32;       // warp row base (0,32,64,96)
    int cb = (w & 1) * 64;        // warp col base (0,64)
    int ntiles = (n + 127) >> 7;
    int stride = gridDim.x;

    float4 va[8];
    int t = blockIdx.x;
    if (t < ntiles) load_A_regs(X, t << 7, 0, n, tid, va);
    __syncthreads();   // W fill complete (covers first store too)

    for (; t < ntiles; t += stride) {
        int trow = t << 7;

        float acc[2][8][4];
#pragma unroll
        for (int mi = 0; mi < 2; mi++)
#pragma unroll
            for (int ni = 0; ni < 8; ni++)
#pragma unroll
                for (int j = 0; j < 4; j++) acc[mi][ni][j] = 0.0f;

#pragma unroll
        for (int c = 0; c < 2; c++) {
            // store prefetched A chunk into smem (convert to tf32 hi/lo)
            store_A_smem(sm, tid, va);
            __syncthreads();

            // prefetch next chunk (this tile's chunk 1, or next tile's chunk 0)
            int tn = (c == 0) ? t : t + stride;
            int cn = c ^ 1;
            if (tn < ntiles) load_A_regs(X, tn << 7, cn, n, tid, va);

            // compute chunk c
#pragma unroll 2
            for (int kb = 0; kb < 8; kb++) {
                int kk = kb * 8 + t4;          // chunk-local A col
                int kB = c * 64 + kb * 8 + t4; // absolute B col
                uint32_t ah[2][4], al[2][4];
#pragma unroll
                for (int mi = 0; mi < 2; mi++) {
                    int r0 = rb + mi * 16 + g;
                    const float* basep = sm + OFF_AHI + r0 * 68 + kk;
                    ah[mi][0] = __float_as_uint(basep[0]);
                    ah[mi][1] = __float_as_uint(basep[8 * 68]);
                    ah[mi][2] = __float_as_uint(basep[4]);
                    ah[mi][3] = __float_as_uint(basep[8 * 68 + 4]);
                    const float* basel = sm + OFF_ALO + r0 * 68 + kk;
                    al[mi][0] = __float_as_uint(basel[0]);
                    al[mi][1] = __float_as_uint(basel[8 * 68]);
                    al[mi][2] = __float_as_uint(basel[4]);
                    al[mi][3] = __float_as_uint(basel[8 * 68 + 4]);
                }
#pragma unroll
                for (int ni = 0; ni < 8; ni++) {
                    int nidx = cb + ni * 8 + g;
                    uint32_t bh[2], bl[2];
                    const float* bph = sm + OFF_BHI + nidx * 132 + kB;
                    const float* bpl = sm + OFF_BLO + nidx * 132 + kB;
                    bh[0] = __float_as_uint(bph[0]);
                    bh[1] = __float_as_uint(bph[4]);
                    bl[0] = __float_as_uint(bpl[0]);
                    bl[1] = __float_as_uint(bpl[4]);
#pragma unroll
                    for (int mi = 0; mi < 2; mi++) {
                        mma8(acc[mi][ni], ah[mi], bh);
                        mma8(acc[mi][ni], ah[mi], bl);
                        mma8(acc[mi][ni], al[mi], bh);
                    }
                }
            }
            __syncthreads();
        }

        // epilogue: acc * dinv -> g_G
#pragma unroll
        for (int mi = 0; mi < 2; mi++) {
            int r0 = trow + rb + mi * 16 + g;
            int r1 = r0 + 8;
            float dv0 = (r0 < n) ? g_dinv[r0] : 0.f;
            float dv1 = (r1 < n) ? g_dinv[r1] : 0.f;
#pragma unroll
            for (int ni = 0; ni < 8; ni++) {
                int col = cb + ni * 8 + t4 * 2;
                if (r0 < n) {
                    float2 o = make_float2(acc[mi][ni][0] * dv0,
                                           acc[mi][ni][1] * dv0);
                    *(float2*)(g_G + (size_t)r0 * 128 + col) = o;
                }
                if (r1 < n) {
                    float2 o = make_float2(acc[mi][ni][2] * dv1,
                                           acc[mi][ni][3] * dv1);
                    *(float2*)(g_G + (size_t)r1 * 128 + col) = o;
                }
            }
        }
    }
}

// ------------------------------------------------------------------
// Fused CSR gather-reduce + finalize (8-deep MLP unroll)
// ------------------------------------------------------------------
__global__ __launch_bounds__(256) void agg_fin_kernel(
    const float* __restrict__ b, int n)
{
    int gid = blockIdx.x * blockDim.x + threadIdx.x;
    int node = gid >> 5;
    int lane = gid & 31;
    if (node >= n) return;

    int beg = g_off[node];
    int end = g_off[node + 1];
    size_t loff = (size_t)lane * 4;

    float4 acc = *(const float4*)(g_G + (size_t)node * 128 + loff);

    int j = beg;
    for (; j + 8 <= end; j += 8) {
        int s0 = g_csr[j + 0], s1 = g_csr[j + 1];
        int s2 = g_csr[j + 2], s3 = g_csr[j + 3];
        int s4 = g_csr[j + 4], s5 = g_csr[j + 5];
        int s6 = g_csr[j + 6], s7 = g_csr[j + 7];
        float4 v0 = *(const float4*)(g_G + (size_t)s0 * 128 + loff);
        float4 v1 = *(const float4*)(g_G + (size_t)s1 * 128 + loff);
        float4 v2 = *(const float4*)(g_G + (size_t)s2 * 128 + loff);
        float4 v3 = *(const float4*)(g_G + (size_t)s3 * 128 + loff);
        float4 v4 = *(const float4*)(g_G + (size_t)s4 * 128 + loff);
        float4 v5 = *(const float4*)(g_G + (size_t)s5 * 128 + loff);
        float4 v6 = *(const float4*)(g_G + (size_t)s6 * 128 + loff);
        float4 v7 = *(const float4*)(g_G + (size_t)s7 * 128 + loff);
        acc.x += (v0.x + v1.x) + (v2.x + v3.x) + ((v4.x + v5.x) + (v6.x + v7.x));
        acc.y += (v0.y + v1.y) + (v2.y + v3.y) + ((v4.y + v5.y) + (v6.y + v7.y));
        acc.z += (v0.z + v1.z) + (v2.z + v3.z) + ((v4.z + v5.z) + (v6.z + v7.z));
        acc.w += (v0.w + v1.w) + (v2.w + v3.w) + ((v4.w + v5.w) + (v6.w + v7.w));
    }
    for (; j + 4 <= end; j += 4) {
        int s0 = g_csr[j + 0], s1 = g_csr[j + 1];
        int s2 = g_csr[j + 2], s3 = g_csr[j + 3];
        float4 v0 = *(const float4*)(g_G + (size_t)s0 * 128 + loff);
        float4 v1 = *(const float4*)(g_G + (size_t)s1 * 128 + loff);
        float4 v2 = *(const float4*)(g_G + (size_t)s2 * 128 + loff);
        float4 v3 = *(const float4*)(g_G + (size_t)s3 * 128 + loff);
        acc.x += (v0.x + v1.x) + (v2.x + v3.x);
        acc.y += (v0.y + v1.y) + (v2.y + v3.y);
        acc.z += (v0.z + v1.z) + (v2.z + v3.z);
        acc.w += (v0.w + v1.w) + (v2.w + v3.w);
    }
    for (; j < end; j++) {
        int s = g_csr[j];
        float4 v = *(const float4*)(g_G + (size_t)s * 128 + loff);
        acc.x += v.x; acc.y += v.y; acc.z += v.z; acc.w += v.w;
    }

    float dv = g_dinv[node];
    float4 bb = *(const float4*)(b + lane * 4);
    float4 o;
    o.x = fmaxf(fmaf(dv, acc.x, bb.x), 0.0f);
    o.y = fmaxf(fmaf(dv, acc.y, bb.y), 0.0f);
    o.z = fmaxf(fmaf(dv, acc.z, bb.z), 0.0f);
    o.w = fmaxf(fmaf(dv, acc.w, bb.w), 0.0f);
    *(float4*)(g_X2 + (size_t)node * 128 + loff) = o;
}

// ------------------------------------------------------------------
// Output GEMM via tf32 mma: out = X2 @ Wout + bout  (K=128, N=40 pad 64)
// Block tile 128x64; warps 4x2, each 32x32 (mi=2, ni=4).
// Reuses the A-chunk layout/helpers of the main gemm.
// ------------------------------------------------------------------
__global__ __launch_bounds__(256) void out_gemm_mma_kernel(
    const float* __restrict__ Wout, const float* __restrict__ bout,
    float* __restrict__ out, int n)
{
    extern __shared__ float sm[];
    int tid = threadIdx.x, w = tid >> 5, lane = tid & 31;
    int g = lane >> 2, t4 = lane & 3;

    // fill Wout hi/lo: Bs[n][k] = Wout[k][n] for n<40, else 0 (64 rows, stride 132)
    for (int i = tid; i < 64 * 128; i += 256) {
        int nn2 = i >> 7, k = i & 127;
        float wv = (nn2 < 40) ? Wout[k * 40 + nn2] : 0.0f;
        uint32_t hi = cvt_tf32(wv);
        uint32_t lo = cvt_tf32(wv - __uint_as_float(hi));
        sm[OFF_BHI + nn2 * 132 + k] = __uint_as_float(hi);
        sm[OFF_BLO + nn2 * 132 + k] = __uint_as_float(lo);
    }

    int rb = (w >> 1) * 32;       // warp row base (0,32,64,96)
    int cb = (w & 1) * 32;        // warp col base (0,32)
    int trow = blockIdx.x << 7;

    float4 va[8];
    load_A_regs(g_X2, trow, 0, n, tid, va);
    __syncthreads();   // B fill complete

    float acc[2][4][4];
#pragma unroll
    for (int mi = 0; mi < 2; mi++)
#pragma unroll
        for (int ni = 0; ni < 4; ni++)
#pragma unroll
            for (int j = 0; j < 4; j++) acc[mi][ni][j] = 0.0f;

#pragma unroll
    for (int c = 0; c < 2; c++) {
        store_A_smem(sm, tid, va);
        __syncthreads();
        if (c == 0) load_A_regs(g_X2, trow, 1, n, tid, va);

#pragma unroll 2
        for (int kb = 0; kb < 8; kb++) {
            int kk = kb * 8 + t4;
            int kB = c * 64 + kb * 8 + t4;
            uint32_t ah[2][4], al[2][4];
#pragma unroll
            for (int mi = 0; mi < 2; mi++) {
                int r0 = rb + mi * 16 + g;
                const float* basep = sm + OFF_AHI + r0 * 68 + kk;
                ah[mi][0] = __float_as_uint(basep[0]);
                ah[mi][1] = __float_as_uint(basep[8 * 68]);
                ah[mi][2] = __float_as_uint(basep[4]);
                ah[mi][3] = __float_as_uint(basep[8 * 68 + 4]);
                const float* basel = sm + OFF_ALO + r0 * 68 + kk;
                al[mi][0] = __float_as_uint(basel[0]);
                al[mi][1] = __float_as_uint(basel[8 * 68]);
                al[mi][2] = __float_as_uint(basel[4]);
                al[mi][3] = __float_as_uint(basel[8 * 68 + 4]);
            }
#pragma unroll
            for (int ni = 0; ni < 4; ni++) {
                int nidx = cb + ni * 8 + g;
                uint32_t bh[2], bl[2];
                const float* bph = sm + OFF_BHI + nidx * 132 + kB;
                const float* bpl = sm + OFF_BLO + nidx * 132 + kB;
                bh[0] = __float_as_uint(bph[0]);
                bh[1] = __float_as_uint(bph[4]);
                bl[0] = __float_as_uint(bpl[0]);
                bl[1] = __float_as_uint(bpl[4]);
#pragma unroll
                for (int mi = 0; mi < 2; mi++) {
                    mma8(acc[mi][ni], ah[mi], bh);
                    mma8(acc[mi][ni], ah[mi], bl);
                    mma8(acc[mi][ni], al[mi], bh);
                }
            }
        }
        __syncthreads();
    }

    // epilogue: out[row][col] = acc + bout[col], only col < 40
#pragma unroll
    for (int mi = 0; mi < 2; mi++) {
        int r0 = trow + rb + mi * 16 + g;
        int r1 = r0 + 8;
#pragma unroll
        for (int ni = 0; ni < 4; ni++) {
            int col = cb + ni * 8 + t4 * 2;
            if (col < 40) {
                float b0 = __ldg(&bout[col]);
                float b1 = __ldg(&bout[col + 1]);
                if (r0 < n) {
                    float2 o = make_float2(acc[mi][ni][0] + b0,
                                           acc[mi][ni][1] + b1);
                    *(float2*)(out + (size_t)r0 * 40 + col) = o;
                }
                if (r1 < n) {
                    float2 o = make_float2(acc[mi][ni][2] + b0,
                                           acc[mi][ni][3] + b1);
                    *(float2*)(out + (size_t)r1 * 40 + col) = o;
                }
            }
        }
    }
}

// ------------------------------------------------------------------
// launch
// ------------------------------------------------------------------
extern "C" void kernel_launch(void* const* d_in, const int* in_sizes, int n_in,
                              void* d_out, int out_size)
{
    const float* x    = (const float*)d_in[0];
    const int*   ei   = (const int*)d_in[1];
    const float* W1   = (const float*)d_in[2];
    const float* b1   = (const float*)d_in[3];
    const float* W2   = (const float*)d_in[4];
    const float* b2   = (const float*)d_in[5];
    const float* Wout = (const float*)d_in[6];
    const float* bout = (const float*)d_in[7];
    float* out = (float*)d_out;

    int n = in_sizes[0] / 128;
    int e = in_sizes[1] / 2;
    const int* src = ei;
    const int* dst = ei + e;

    cudaFuncSetAttribute(gemm_mma_kernel,
                         cudaFuncAttributeMaxDynamicSharedMemorySize, GEMM_SMEM_B);
    cudaFuncSetAttribute(out_gemm_mma_kernel,
                         cudaFuncAttributeMaxDynamicSharedMemorySize, GEMM_SMEM_B);

    int nb_n = (n + 255) / 256;
    int nb_e = (e + 255) / 256;
    int nb_scan = (n + 1023) / 1024;
    long long agg_threads = (long long)n * 32;
    int nb_agg = (int)((agg_threads + 255) / 256);
    int ntiles = (n + 127) / 128;

    // CSR build (g_cnt zeroed on load and re-zeroed by scan_local each call)
    count_kernel<<<nb_e, 256>>>(dst, e);
    scan_local_kernel<<<nb_scan, 256>>>(n);
    scan_bsums_kernel<<<1, 1024>>>(nb_scan);
    scan_add_kernel<<<nb_n, 256>>>(n, e);
    scatter_kernel<<<nb_e, 256>>>(src, dst, e);

    // layer 1
    gemm_mma_kernel<<<152, 256, GEMM_SMEM_B>>>(x, W1, n, 0);
    agg_fin_kernel<<<nb_agg, 256>>>(b1, n);

    // layer 2
    gemm_mma_kernel<<<152, 256, GEMM_SMEM_B>>>(nullptr, W2, n, 1);
    agg_fin_kernel<<<nb_agg, 256>>>(b2, n);

    // output projection (tensor core)
    out_gemm_mma_kernel<<<ntiles, 256, GEMM_SMEM_B>>>(Wout, bout, out, n);
}

// round 15
// speedup vs baseline: 1.2586x; 1.2586x over previous
#include <cuda_runtime.h>
#include <cuda_bf16.h>
#include <cstdint>

#define NN 100000
#define EE 1600000

// ---- device scratch ----
__device__ int   g_cnt[NN];       // zero-init by CUDA; re-zeroed each call in scan_local
__device__ int   g_off[NN + 1];
__device__ int   g_cur[NN];
__device__ int   g_bsum[1024];
__device__ int   g_csr[EE];
__device__ float g_dinv[NN];
__device__ float g_G[NN * 128];
__device__ float g_X2[NN * 128];

// ------------------------------------------------------------------
// CSR build
// ------------------------------------------------------------------
__global__ void count_kernel(const int* __restrict__ dst, int e) {
    int i = blockIdx.x * blockDim.x + threadIdx.x;
    if (i < e) atomicAdd(&g_cnt[dst[i]], 1);
}
__global__ __launch_bounds__(256) void scan_local_kernel(int n) {
    __shared__ int ssum[256];
    int t = threadIdx.x;
    int base = blockIdx.x * 1024 + t * 4;
    int c0 = (base + 0 < n) ? g_cnt[base + 0] : 0;
    int c1 = (base + 1 < n) ? g_cnt[base + 1] : 0;
    int c2 = (base + 2 < n) ? g_cnt[base + 2] : 0;
    int c3 = (base + 3 < n) ? g_cnt[base + 3] : 0;
    if (base + 0 < n) { g_dinv[base + 0] = rsqrtf((float)c0 + 1.0f); g_cnt[base + 0] = 0; }
    if (base + 1 < n) { g_dinv[base + 1] = rsqrtf((float)c1 + 1.0f); g_cnt[base + 1] = 0; }
    if (base + 2 < n) { g_dinv[base + 2] = rsqrtf((float)c2 + 1.0f); g_cnt[base + 2] = 0; }
    if (base + 3 < n) { g_dinv[base + 3] = rsqrtf((float)c3 + 1.0f); g_cnt[base + 3] = 0; }
    int tsum = c0 + c1 + c2 + c3;
    ssum[t] = tsum;
    __syncthreads();
    for (int off = 1; off < 256; off <<= 1) {
        int v = (t >= off) ? ssum[t - off] : 0;
        __syncthreads();
        ssum[t] += v;
        __syncthreads();
    }
    int excl = ssum[t] - tsum;
    if (base + 0 < n) g_off[base + 0] = excl;
    if (base + 1 < n) g_off[base + 1] = excl + c0;
    if (base + 2 < n) g_off[base + 2] = excl + c0 + c1;
    if (base + 3 < n) g_off[base + 3] = excl + c0 + c1 + c2;
    if (t == 255) g_bsum[blockIdx.x] = ssum[255];
}
__global__ __launch_bounds__(1024) void scan_bsums_kernel(int nb) {
    __shared__ int s[1024];
    int t = threadIdx.x;
    int v = (t < nb) ? g_bsum[t] : 0;
    s[t] = v;
    __syncthreads();
    for (int off = 1; off < 1024; off <<= 1) {
        int u = (t >= off) ? s[t - off] : 0;
        __syncthreads();
        s[t] += u;
        __syncthreads();
    }
    if (t < nb) g_bsum[t] = s[t] - v;
}
__global__ void scan_add_kernel(int n, int e) {
    int i = blockIdx.x * blockDim.x + threadIdx.x;
    if (i < n) {
        int v = g_off[i] + g_bsum[i >> 10];
        g_off[i] = v;
        g_cur[i] = v;
    }
    if (i == 0) g_off[n] = e;
}
__global__ void scatter_kernel(const int* __restrict__ src,
                               const int* __restrict__ dst, int e) {
    int i = blockIdx.x * blockDim.x + threadIdx.x;
    if (i < e) {
        int pos = atomicAdd(&g_cur[dst[i]], 1);
        g_csr[pos] = src[i];
    }
}

// ------------------------------------------------------------------
// bf16 3-term split GEMM via mma.sync.m16n8k16 (sm_80 PTX)
// ------------------------------------------------------------------
__device__ __forceinline__ void mma16(float* d, const uint32_t* a, const uint32_t* b) {
    asm volatile(
        "mma.sync.aligned.m16n8k16.row.col.f32.bf16.bf16.f32 "
        "{%0,%1,%2,%3}, {%4,%5,%6,%7}, {%8,%9}, {%0,%1,%2,%3};"
        : "+f"(d[0]), "+f"(d[1]), "+f"(d[2]), "+f"(d[3])
        : "r"(a[0]), "r"(a[1]), "r"(a[2]), "r"(a[3]), "r"(b[0]), "r"(b[1]));
}

// split x into bf16 hi + bf16 lo residual; pack (x0,x1) pairs (x0 in low half)
__device__ __forceinline__ uint32_t bf16_split_pack(float x0, float x1, uint32_t& lopack) {
    __nv_bfloat16 h0 = __float2bfloat16(x0);
    __nv_bfloat16 h1 = __float2bfloat16(x1);
    float r0 = x0 - __bfloat162float(h0);
    float r1 = x1 - __bfloat162float(h1);
    __nv_bfloat16 l0 = __float2bfloat16(r0);
    __nv_bfloat16 l1 = __float2bfloat16(r1);
    lopack = ((uint32_t)__bfloat16_as_ushort(l1) << 16) | (uint32_t)__bfloat16_as_ushort(l0);
    return ((uint32_t)__bfloat16_as_ushort(h1) << 16) | (uint32_t)__bfloat16_as_ushort(h0);
}

// smem (u32 units): Bhi[128 rows x 68], Blo, Ahi[128 x 36], Alo
// strides 68/36 u32 == 4 mod 32 -> fragment loads hit banks 4g+t4: conflict-free
#define OFF_BHI 0
#define OFF_BLO 8704
#define OFF_AHI 17408
#define OFF_ALO 22016
#define GEMM_SMEM_U 26624
#define GEMM_SMEM_B (GEMM_SMEM_U * 4)   // 106496 B

// load one A chunk (K=64 cols starting at c*64) into 8 float4 regs
__device__ __forceinline__ void load_A_regs(
    const float* __restrict__ X, int trow, int c, int n, int tid, float4* va)
{
#pragma unroll
    for (int j = 0; j < 8; j++) {
        int i4 = tid + j * 256;
        int m = i4 >> 4, q = i4 & 15;
        int row = trow + m;
        va[j] = make_float4(0.f, 0.f, 0.f, 0.f);
        if (row < n)
            va[j] = *(const float4*)(X + (size_t)row * 128 + c * 64 + q * 4);
    }
}

// convert regs -> bf16 hi/lo pairs and store to smem A (chunk-local 32 u32 + pad)
__device__ __forceinline__ void store_A_smem(uint32_t* smu, int tid, const float4* va)
{
#pragma unroll
    for (int j = 0; j < 8; j++) {
        int i4 = tid + j * 256;
        int m = i4 >> 4, q = i4 & 15;
        float4 v = va[j];
        uint32_t lo0, lo1;
        uint32_t hi0 = bf16_split_pack(v.x, v.y, lo0);
        uint32_t hi1 = bf16_split_pack(v.z, v.w, lo1);
        int base = m * 36 + 2 * q;
        smu[OFF_AHI + base]     = hi0;
        smu[OFF_AHI + base + 1] = hi1;
        smu[OFF_ALO + base]     = lo0;
        smu[OFF_ALO + base + 1] = lo1;
    }
}

// G = (X @ W) * dinv[row]; persistent; M-tile 128, N=128, K=128 (2 chunks of 64)
__global__ __launch_bounds__(256) void gemm_mma_kernel(
    const float* __restrict__ Xext, const float* __restrict__ W,
    int n, int use_x2)
{
    extern __shared__ uint32_t smu[];
    const float* X = use_x2 ? g_X2 : Xext;
    int tid = threadIdx.x, w = tid >> 5, lane = tid & 31;
    int g = lane >> 2, t4 = lane & 3;

    // fill W hi/lo once: B[n][k] = W[k][n], bf16 pairs, row stride 68 u32
    for (int i = tid; i < 64 * 128; i += 256) {
        int ku = i >> 7, nn2 = i & 127;
        float x0 = W[(2 * ku) * 128 + nn2];
        float x1 = W[(2 * ku + 1) * 128 + nn2];
        uint32_t lo;
        uint32_t hi = bf16_split_pack(x0, x1, lo);
        smu[OFF_BHI + nn2 * 68 + ku] = hi;
        smu[OFF_BLO + nn2 * 68 + ku] = lo;
    }

    int rb = (w >> 1) * 32;       // warp row base (0,32,64,96)
    int cb = (w & 1) * 64;        // warp col base (0,64)
    int ntiles = (n + 127) >> 7;
    int stride = gridDim.x;

    float4 va[8];
    int t = blockIdx.x;
    if (t < ntiles) load_A_regs(X, t << 7, 0, n, tid, va);
    __syncthreads();   // W fill complete

    for (; t < ntiles; t += stride) {
        int trow = t << 7;

        float acc[2][8][4];
#pragma unroll
        for (int mi = 0; mi < 2; mi++)
#pragma unroll
            for (int ni = 0; ni < 8; ni++)
#pragma unroll
                for (int j = 0; j < 4; j++) acc[mi][ni][j] = 0.0f;

#pragma unroll
        for (int c = 0; c < 2; c++) {
            store_A_smem(smu, tid, va);
            __syncthreads();

            // prefetch next chunk (this tile's chunk 1, or next tile's chunk 0)
            int tn = (c == 0) ? t : t + stride;
            int cn = c ^ 1;
            if (tn < ntiles) load_A_regs(X, tn << 7, cn, n, tid, va);

            // compute chunk c: 4 k16 steps
#pragma unroll
            for (int s = 0; s < 4; s++) {
                int ka = s * 8 + t4;            // A u32 idx within chunk
                int kB = c * 32 + s * 8 + t4;   // B u32 idx (full K)
                uint32_t ah[2][4], al[2][4];
#pragma unroll
                for (int mi = 0; mi < 2; mi++) {
                    int r0 = rb + mi * 16 + g;
                    const uint32_t* ph = smu + OFF_AHI + r0 * 36 + ka;
                    ah[mi][0] = ph[0];
                    ah[mi][1] = ph[8 * 36];
                    ah[mi][2] = ph[4];
                    ah[mi][3] = ph[8 * 36 + 4];
                    const uint32_t* pl = smu + OFF_ALO + r0 * 36 + ka;
                    al[mi][0] = pl[0];
                    al[mi][1] = pl[8 * 36];
                    al[mi][2] = pl[4];
                    al[mi][3] = pl[8 * 36 + 4];
                }
#pragma unroll
                for (int ni = 0; ni < 8; ni++) {
                    int nidx = cb + ni * 8 + g;
                    const uint32_t* pbh = smu + OFF_BHI + nidx * 68 + kB;
                    const uint32_t* pbl = smu + OFF_BLO + nidx * 68 + kB;
                    uint32_t bh[2] = {pbh[0], pbh[4]};
                    uint32_t bl[2] = {pbl[0], pbl[4]};
#pragma unroll
                    for (int mi = 0; mi < 2; mi++) {
                        mma16(acc[mi][ni], ah[mi], bh);
                        mma16(acc[mi][ni], ah[mi], bl);
                        mma16(acc[mi][ni], al[mi], bh);
                    }
                }
            }
            __syncthreads();
        }

        // epilogue: acc * dinv -> g_G
#pragma unroll
        for (int mi = 0; mi < 2; mi++) {
            int r0 = trow + rb + mi * 16 + g;
            int r1 = r0 + 8;
            float dv0 = (r0 < n) ? g_dinv[r0] : 0.f;
            float dv1 = (r1 < n) ? g_dinv[r1] : 0.f;
#pragma unroll
            for (int ni = 0; ni < 8; ni++) {
                int col = cb + ni * 8 + t4 * 2;
                if (r0 < n) {
                    float2 o = make_float2(acc[mi][ni][0] * dv0,
                                           acc[mi][ni][1] * dv0);
                    *(float2*)(g_G + (size_t)r0 * 128 + col) = o;
                }
                if (r1 < n) {
                    float2 o = make_float2(acc[mi][ni][2] * dv1,
                                           acc[mi][ni][3] * dv1);
                    *(float2*)(g_G + (size_t)r1 * 128 + col) = o;
                }
            }
        }
    }
}

// ------------------------------------------------------------------
// Fused CSR gather-reduce + finalize (8-deep MLP unroll)
// ------------------------------------------------------------------
__global__ __launch_bounds__(256) void agg_fin_kernel(
    const float* __restrict__ b, int n)
{
    int gid = blockIdx.x * blockDim.x + threadIdx.x;
    int node = gid >> 5;
    int lane = gid & 31;
    if (node >= n) return;

    int beg = g_off[node];
    int end = g_off[node + 1];
    size_t loff = (size_t)lane * 4;

    float4 acc = *(const float4*)(g_G + (size_t)node * 128 + loff);

    int j = beg;
    for (; j + 8 <= end; j += 8) {
        int s0 = g_csr[j + 0], s1 = g_csr[j + 1];
        int s2 = g_csr[j + 2], s3 = g_csr[j + 3];
        int s4 = g_csr[j + 4], s5 = g_csr[j + 5];
        int s6 = g_csr[j + 6], s7 = g_csr[j + 7];
        float4 v0 = *(const float4*)(g_G + (size_t)s0 * 128 + loff);
        float4 v1 = *(const float4*)(g_G + (size_t)s1 * 128 + loff);
        float4 v2 = *(const float4*)(g_G + (size_t)s2 * 128 + loff);
        float4 v3 = *(const float4*)(g_G + (size_t)s3 * 128 + loff);
        float4 v4 = *(const float4*)(g_G + (size_t)s4 * 128 + loff);
        float4 v5 = *(const float4*)(g_G + (size_t)s5 * 128 + loff);
        float4 v6 = *(const float4*)(g_G + (size_t)s6 * 128 + loff);
        float4 v7 = *(const float4*)(g_G + (size_t)s7 * 128 + loff);
        acc.x += (v0.x + v1.x) + (v2.x + v3.x) + ((v4.x + v5.x) + (v6.x + v7.x));
        acc.y += (v0.y + v1.y) + (v2.y + v3.y) + ((v4.y + v5.y) + (v6.y + v7.y));
        acc.z += (v0.z + v1.z) + (v2.z + v3.z) + ((v4.z + v5.z) + (v6.z + v7.z));
        acc.w += (v0.w + v1.w) + (v2.w + v3.w) + ((v4.w + v5.w) + (v6.w + v7.w));
    }
    for (; j + 4 <= end; j += 4) {
        int s0 = g_csr[j + 0], s1 = g_csr[j + 1];
        int s2 = g_csr[j + 2], s3 = g_csr[j + 3];
        float4 v0 = *(const float4*)(g_G + (size_t)s0 * 128 + loff);
        float4 v1 = *(const float4*)(g_G + (size_t)s1 * 128 + loff);
        float4 v2 = *(const float4*)(g_G + (size_t)s2 * 128 + loff);
        float4 v3 = *(const float4*)(g_G + (size_t)s3 * 128 + loff);
        acc.x += (v0.x + v1.x) + (v2.x + v3.x);
        acc.y += (v0.y + v1.y) + (v2.y + v3.y);
        acc.z += (v0.z + v1.z) + (v2.z + v3.z);
        acc.w += (v0.w + v1.w) + (v2.w + v3.w);
    }
    for (; j < end; j++) {
        int s = g_csr[j];
        float4 v = *(const float4*)(g_G + (size_t)s * 128 + loff);
        acc.x += v.x; acc.y += v.y; acc.z += v.z; acc.w += v.w;
    }

    float dv = g_dinv[node];
    float4 bb = *(const float4*)(b + lane * 4);
    float4 o;
    o.x = fmaxf(fmaf(dv, acc.x, bb.x), 0.0f);
    o.y = fmaxf(fmaf(dv, acc.y, bb.y), 0.0f);
    o.z = fmaxf(fmaf(dv, acc.z, bb.z), 0.0f);
    o.w = fmaxf(fmaf(dv, acc.w, bb.w), 0.0f);
    *(float4*)(g_X2 + (size_t)node * 128 + loff) = o;
}

// ------------------------------------------------------------------
// Output GEMM via bf16 split mma: out = X2 @ Wout + bout (K=128, N=40 pad 64)
// Block tile 128x64; warps 4x2, each 32x32 (mi=2, ni=4).
// ------------------------------------------------------------------
__global__ __launch_bounds__(256) void out_gemm_mma_kernel(
    const float* __restrict__ Wout, const float* __restrict__ bout,
    float* __restrict__ out, int n)
{
    extern __shared__ uint32_t smu[];
    int tid = threadIdx.x, w = tid >> 5, lane = tid & 31;
    int g = lane >> 2, t4 = lane & 3;

    // fill Wout hi/lo: B[n][k] = Wout[k][n] for n<40, else 0 (64 rows x 68 u32)
    for (int i = tid; i < 64 * 64; i += 256) {
        int ku = i >> 6, nn2 = i & 63;
        float x0 = (nn2 < 40) ? Wout[(2 * ku) * 40 + nn2] : 0.0f;
        float x1 = (nn2 < 40) ? Wout[(2 * ku + 1) * 40 + nn2] : 0.0f;
        uint32_t lo;
        uint32_t hi = bf16_split_pack(x0, x1, lo);
        smu[OFF_BHI + nn2 * 68 + ku] = hi;
        smu[OFF_BLO + nn2 * 68 + ku] = lo;
    }

    int rb = (w >> 1) * 32;       // warp row base (0,32,64,96)
    int cb = (w & 1) * 32;        // warp col base (0,32)
    int trow = blockIdx.x << 7;

    float4 va[8];
    load_A_regs(g_X2, trow, 0, n, tid, va);
    __syncthreads();   // B fill complete

    float acc[2][4][4];
#pragma unroll
    for (int mi = 0; mi < 2; mi++)
#pragma unroll
        for (int ni = 0; ni < 4; ni++)
#pragma unroll
            for (int j = 0; j < 4; j++) acc[mi][ni][j] = 0.0f;

#pragma unroll
    for (int c = 0; c < 2; c++) {
        store_A_smem(smu, tid, va);
        __syncthreads();
        if (c == 0) load_A_regs(g_X2, trow, 1, n, tid, va);

#pragma unroll
        for (int s = 0; s < 4; s++) {
            int ka = s * 8 + t4;
            int kB = c * 32 + s * 8 + t4;
            uint32_t ah[2][4], al[2][4];
#pragma unroll
            for (int mi = 0; mi < 2; mi++) {
                int r0 = rb + mi * 16 + g;
                const uint32_t* ph = smu + OFF_AHI + r0 * 36 + ka;
                ah[mi][0] = ph[0];
                ah[mi][1] = ph[8 * 36];
                ah[mi][2] = ph[4];
                ah[mi][3] = ph[8 * 36 + 4];
                const uint32_t* pl = smu + OFF_ALO + r0 * 36 + ka;
                al[mi][0] = pl[0];
                al[mi][1] = pl[8 * 36];
                al[mi][2] = pl[4];
                al[mi][3] = pl[8 * 36 + 4];
            }
#pragma unroll
            for (int ni = 0; ni < 4; ni++) {
                int nidx = cb + ni * 8 + g;
                const uint32_t* pbh = smu + OFF_BHI + nidx * 68 + kB;
                const uint32_t* pbl = smu + OFF_BLO + nidx * 68 + kB;
                uint32_t bh[2] = {pbh[0], pbh[4]};
                uint32_t bl[2] = {pbl[0], pbl[4]};
#pragma unroll
                for (int mi = 0; mi < 2; mi++) {
                    mma16(acc[mi][ni], ah[mi], bh);
                    mma16(acc[mi][ni], ah[mi], bl);
                    mma16(acc[mi][ni], al[mi], bh);
                }
            }
        }
        __syncthreads();
    }

    // epilogue: out[row][col] = acc + bout[col], only col < 40
#pragma unroll
    for (int mi = 0; mi < 2; mi++) {
        int r0 = trow + rb + mi * 16 + g;
        int r1 = r0 + 8;
#pragma unroll
        for (int ni = 0; ni < 4; ni++) {
            int col = cb + ni * 8 + t4 * 2;
            if (col < 40) {
                float b0 = __ldg(&bout[col]);
                float b1 = __ldg(&bout[col + 1]);
                if (r0 < n) {
                    float2 o = make_float2(acc[mi][ni][0] + b0,
                                           acc[mi][ni][1] + b1);
                    *(float2*)(out + (size_t)r0 * 40 + col) = o;
                }
                if (r1 < n) {
                    float2 o = make_float2(acc[mi][ni][2] + b0,
                                           acc[mi][ni][3] + b1);
                    *(float2*)(out + (size_t)r1 * 40 + col) = o;
                }
            }
        }
    }
}

// ------------------------------------------------------------------
// launch
// ------------------------------------------------------------------
extern "C" void kernel_launch(void* const* d_in, const int* in_sizes, int n_in,
                              void* d_out, int out_size)
{
    const float* x    = (const float*)d_in[0];
    const int*   ei   = (const int*)d_in[1];
    const float* W1   = (const float*)d_in[2];
    const float* b1   = (const float*)d_in[3];
    const float* W2   = (const float*)d_in[4];
    const float* b2   = (const float*)d_in[5];
    const float* Wout = (const float*)d_in[6];
    const float* bout = (const float*)d_in[7];
    float* out = (float*)d_out;

    int n = in_sizes[0] / 128;
    int e = in_sizes[1] / 2;
    const int* src = ei;
    const int* dst = ei + e;

    cudaFuncSetAttribute(gemm_mma_kernel,
                         cudaFuncAttributeMaxDynamicSharedMemorySize, GEMM_SMEM_B);
    cudaFuncSetAttribute(out_gemm_mma_kernel,
                         cudaFuncAttributeMaxDynamicSharedMemorySize, GEMM_SMEM_B);

    int nb_n = (n + 255) / 256;
    int nb_e = (e + 255) / 256;
    int nb_scan = (n + 1023) / 1024;
    long long agg_threads = (long long)n * 32;
    int nb_agg = (int)((agg_threads + 255) / 256);
    int ntiles = (n + 127) / 128;

    // CSR build (g_cnt zeroed on load and re-zeroed by scan_local each call)
    count_kernel<<<nb_e, 256>>>(dst, e);
    scan_local_kernel<<<nb_scan, 256>>>(n);
    scan_bsums_kernel<<<1, 1024>>>(nb_scan);
    scan_add_kernel<<<nb_n, 256>>>(n, e);
    scatter_kernel<<<nb_e, 256>>>(src, dst, e);

    // layer 1
    gemm_mma_kernel<<<152, 256, GEMM_SMEM_B>>>(x, W1, n, 0);
    agg_fin_kernel<<<nb_agg, 256>>>(b1, n);

    // layer 2
    gemm_mma_kernel<<<152, 256, GEMM_SMEM_B>>>(nullptr, W2, n, 1);
    agg_fin_kernel<<<nb_agg, 256>>>(b2, n);

    // output projection (bf16 split tensor core)
    out_gemm_mma_kernel<<<ntiles, 256, GEMM_SMEM_B>>>(Wout, bout, out, n);
}

// round 16
// speedup vs baseline: 1.2742x; 1.0124x over previous
#include <cuda_runtime.h>
#include <cuda_bf16.h>
#include <cstdint>

#define NN 100000
#define EE 1600000

// ---- device scratch ----
__device__ int   g_cnt[NN];       // zero-init by CUDA; re-zeroed each call in scan_local
__device__ int   g_off[NN + 1];
__device__ int   g_cur[NN];
__device__ int   g_bsum[1024];
__device__ int   g_csr[EE];
__device__ float g_dinv[NN];
__device__ float g_G[NN * 128];
__device__ float g_X2[NN * 128];

// ------------------------------------------------------------------
// CSR build
// ------------------------------------------------------------------
__global__ void count_kernel(const int* __restrict__ dst, int e) {
    int i = blockIdx.x * blockDim.x + threadIdx.x;
    if (i < e) atomicAdd(&g_cnt[dst[i]], 1);
}
__global__ __launch_bounds__(256) void scan_local_kernel(int n) {
    __shared__ int ssum[256];
    int t = threadIdx.x;
    int base = blockIdx.x * 1024 + t * 4;
    int c0 = (base + 0 < n) ? g_cnt[base + 0] : 0;
    int c1 = (base + 1 < n) ? g_cnt[base + 1] : 0;
    int c2 = (base + 2 < n) ? g_cnt[base + 2] : 0;
    int c3 = (base + 3 < n) ? g_cnt[base + 3] : 0;
    if (base + 0 < n) { g_dinv[base + 0] = rsqrtf((float)c0 + 1.0f); g_cnt[base + 0] = 0; }
    if (base + 1 < n) { g_dinv[base + 1] = rsqrtf((float)c1 + 1.0f); g_cnt[base + 1] = 0; }
    if (base + 2 < n) { g_dinv[base + 2] = rsqrtf((float)c2 + 1.0f); g_cnt[base + 2] = 0; }
    if (base + 3 < n) { g_dinv[base + 3] = rsqrtf((float)c3 + 1.0f); g_cnt[base + 3] = 0; }
    int tsum = c0 + c1 + c2 + c3;
    ssum[t] = tsum;
    __syncthreads();
    for (int off = 1; off < 256; off <<= 1) {
        int v = (t >= off) ? ssum[t - off] : 0;
        __syncthreads();
        ssum[t] += v;
        __syncthreads();
    }
    int excl = ssum[t] - tsum;
    if (base + 0 < n) g_off[base + 0] = excl;
    if (base + 1 < n) g_off[base + 1] = excl + c0;
    if (base + 2 < n) g_off[base + 2] = excl + c0 + c1;
    if (base + 3 < n) g_off[base + 3] = excl + c0 + c1 + c2;
    if (t == 255) g_bsum[blockIdx.x] = ssum[255];
}
__global__ __launch_bounds__(1024) void scan_bsums_kernel(int nb) {
    __shared__ int s[1024];
    int t = threadIdx.x;
    int v = (t < nb) ? g_bsum[t] : 0;
    s[t] = v;
    __syncthreads();
    for (int off = 1; off < 1024; off <<= 1) {
        int u = (t >= off) ? s[t - off] : 0;
        __syncthreads();
        s[t] += u;
        __syncthreads();
    }
    if (t < nb) g_bsum[t] = s[t] - v;
}
__global__ void scan_add_kernel(int n, int e) {
    int i = blockIdx.x * blockDim.x + threadIdx.x;
    if (i < n) {
        int v = g_off[i] + g_bsum[i >> 10];
        g_off[i] = v;
        g_cur[i] = v;
    }
    if (i == 0) g_off[n] = e;
}
__global__ void scatter_kernel(const int* __restrict__ src,
                               const int* __restrict__ dst, int e) {
    int i = blockIdx.x * blockDim.x + threadIdx.x;
    if (i < e) {
        int pos = atomicAdd(&g_cur[dst[i]], 1);
        g_csr[pos] = src[i];
    }
}

// ------------------------------------------------------------------
// bf16 3-term split GEMM via mma.sync.m16n8k16 + ldmatrix (sm_80 PTX)
// ------------------------------------------------------------------
__device__ __forceinline__ void mma16(float* d, const uint32_t* a, const uint32_t* b) {
    asm volatile(
        "mma.sync.aligned.m16n8k16.row.col.f32.bf16.bf16.f32 "
        "{%0,%1,%2,%3}, {%4,%5,%6,%7}, {%8,%9}, {%0,%1,%2,%3};"
        : "+f"(d[0]), "+f"(d[1]), "+f"(d[2]), "+f"(d[3])
        : "r"(a[0]), "r"(a[1]), "r"(a[2]), "r"(a[3]), "r"(b[0]), "r"(b[1]));
}

#define LDMX4(d, addr) \
    asm volatile("ldmatrix.sync.aligned.m8n8.x4.shared.b16 {%0,%1,%2,%3}, [%4];" \
        : "=r"((d)[0]), "=r"((d)[1]), "=r"((d)[2]), "=r"((d)[3]) : "r"(addr))

// split x into bf16 hi + bf16 lo residual; pack (x0,x1) pairs (x0 in low half)
__device__ __forceinline__ uint32_t bf16_split_pack(float x0, float x1, uint32_t& lopack) {
    __nv_bfloat16 h0 = __float2bfloat16(x0);
    __nv_bfloat16 h1 = __float2bfloat16(x1);
    float r0 = x0 - __bfloat162float(h0);
    float r1 = x1 - __bfloat162float(h1);
    __nv_bfloat16 l0 = __float2bfloat16(r0);
    __nv_bfloat16 l1 = __float2bfloat16(r1);
    lopack = ((uint32_t)__bfloat16_as_ushort(l1) << 16) | (uint32_t)__bfloat16_as_ushort(l0);
    return ((uint32_t)__bfloat16_as_ushort(h1) << 16) | (uint32_t)__bfloat16_as_ushort(h0);
}

// smem (u32 units): Bhi[128 rows x 68], Blo, Ahi[128 x 36], Alo
// strides 68/36 u32 == 4 mod 32 -> 8-row ldmatrix phases conflict-free
#define OFF_BHI 0
#define OFF_BLO 8704
#define OFF_AHI 17408
#define OFF_ALO 22016
#define GEMM_SMEM_U 26624
#define GEMM_SMEM_B (GEMM_SMEM_U * 4)   // 106496 B

// load one A chunk (K=64 cols starting at c*64) into 8 float4 regs
__device__ __forceinline__ void load_A_regs(
    const float* __restrict__ X, int trow, int c, int n, int tid, float4* va)
{
#pragma unroll
    for (int j = 0; j < 8; j++) {
        int i4 = tid + j * 256;
        int m = i4 >> 4, q = i4 & 15;
        int row = trow + m;
        va[j] = make_float4(0.f, 0.f, 0.f, 0.f);
        if (row < n)
            va[j] = *(const float4*)(X + (size_t)row * 128 + c * 64 + q * 4);
    }
}

// convert regs -> bf16 hi/lo pairs and store to smem A (chunk-local 32 u32 + pad)
__device__ __forceinline__ void store_A_smem(uint32_t* smu, int tid, const float4* va)
{
#pragma unroll
    for (int j = 0; j < 8; j++) {
        int i4 = tid + j * 256;
        int m = i4 >> 4, q = i4 & 15;
        float4 v = va[j];
        uint32_t lo0, lo1;
        uint32_t hi0 = bf16_split_pack(v.x, v.y, lo0);
        uint32_t hi1 = bf16_split_pack(v.z, v.w, lo1);
        int base = m * 36 + 2 * q;
        smu[OFF_AHI + base]     = hi0;
        smu[OFF_AHI + base + 1] = hi1;
        smu[OFF_ALO + base]     = lo0;
        smu[OFF_ALO + base + 1] = lo1;
    }
}

// G = (X @ W) * dinv[row]; persistent; M-tile 128, N=128, K=128 (2 chunks of 64)
__global__ __launch_bounds__(256) void gemm_mma_kernel(
    const float* __restrict__ Xext, const float* __restrict__ W,
    int n, int use_x2)
{
    extern __shared__ uint32_t smu[];
    const float* X = use_x2 ? g_X2 : Xext;
    int tid = threadIdx.x, w = tid >> 5, lane = tid & 31;
    int g = lane >> 2, t4 = lane & 3;

    // fill W hi/lo once: B[n][k] = W[k][n], bf16 pairs, row stride 68 u32
    for (int i = tid; i < 64 * 128; i += 256) {
        int ku = i >> 7, nn2 = i & 127;
        float x0 = W[(2 * ku) * 128 + nn2];
        float x1 = W[(2 * ku + 1) * 128 + nn2];
        uint32_t lo;
        uint32_t hi = bf16_split_pack(x0, x1, lo);
        smu[OFF_BHI + nn2 * 68 + ku] = hi;
        smu[OFF_BLO + nn2 * 68 + ku] = lo;
    }

    int rb = (w >> 1) * 32;       // warp row base (0,32,64,96)
    int cb = (w & 1) * 64;        // warp col base (0,64)
    int ntiles = (n + 127) >> 7;
    int stride = gridDim.x;

    // ldmatrix per-lane base addresses (u32 units -> bytes at use)
    uint32_t sbase = (uint32_t)__cvta_generic_to_shared(smu);
    // A: lanes 0-15 rows (lane&15) k-low; lanes 16-31 same rows k-high (+4 u32)
    uint32_t a_row = (uint32_t)(rb + (lane & 15));
    uint32_t a_base_hi = sbase + (OFF_AHI + a_row * 36 + ((lane >> 4) << 2)) * 4;
    uint32_t a_base_lo = a_base_hi + (OFF_ALO - OFF_AHI) * 4;
    // B: grp = lane>>3: 0: ni0 k-lo, 1: ni0 k-hi, 2: ni0+1 k-lo, 3: ni0+1 k-hi
    uint32_t grp = (uint32_t)(lane >> 3);
    uint32_t b_row = (uint32_t)(cb + (lane & 7) + ((grp >> 1) << 3));
    uint32_t b_base_hi = sbase + (OFF_BHI + b_row * 68 + ((grp & 1) << 2)) * 4;
    uint32_t b_base_lo = b_base_hi + (OFF_BLO - OFF_BHI) * 4;

    float4 va[8];
    int t = blockIdx.x;
    if (t < ntiles) load_A_regs(X, t << 7, 0, n, tid, va);
    __syncthreads();   // W fill complete

    for (; t < ntiles; t += stride) {
        int trow = t << 7;

        float acc[2][8][4];
#pragma unroll
        for (int mi = 0; mi < 2; mi++)
#pragma unroll
            for (int ni = 0; ni < 8; ni++)
#pragma unroll
                for (int j = 0; j < 4; j++) acc[mi][ni][j] = 0.0f;

#pragma unroll
        for (int c = 0; c < 2; c++) {
            store_A_smem(smu, tid, va);
            __syncthreads();

            // prefetch next chunk (this tile's chunk 1, or next tile's chunk 0)
            int tn = (c == 0) ? t : t + stride;
            int cn = c ^ 1;
            if (tn < ntiles) load_A_regs(X, tn << 7, cn, n, tid, va);

            // compute chunk c: 4 k16 steps
#pragma unroll
            for (int s = 0; s < 4; s++) {
                uint32_t aoff = (uint32_t)(s * 8) * 4;            // chunk-local
                uint32_t boff = (uint32_t)(c * 32 + s * 8) * 4;   // full K
                uint32_t ah[2][4], al[2][4];
#pragma unroll
                for (int mi = 0; mi < 2; mi++) {
                    LDMX4(ah[mi], a_base_hi + (uint32_t)(mi * 576) * 4 + aoff);
                    LDMX4(al[mi], a_base_lo + (uint32_t)(mi * 576) * 4 + aoff);
                }
#pragma unroll
                for (int nj = 0; nj < 4; nj++) {
                    uint32_t bh2[4], bl2[4];
                    LDMX4(bh2, b_base_hi + (uint32_t)(nj * 1088) * 4 + boff);
                    LDMX4(bl2, b_base_lo + (uint32_t)(nj * 1088) * 4 + boff);
#pragma unroll
                    for (int p = 0; p < 2; p++) {
                        int ni = 2 * nj + p;
#pragma unroll
                        for (int mi = 0; mi < 2; mi++) {
                            mma16(acc[mi][ni], ah[mi], bh2 + 2 * p);
                            mma16(acc[mi][ni], ah[mi], bl2 + 2 * p);
                            mma16(acc[mi][ni], al[mi], bh2 + 2 * p);
                        }
                    }
                }
            }
            __syncthreads();
        }

        // epilogue: acc * dinv -> g_G
#pragma unroll
        for (int mi = 0; mi < 2; mi++) {
            int r0 = trow + rb + mi * 16 + g;
            int r1 = r0 + 8;
            float dv0 = (r0 < n) ? g_dinv[r0] : 0.f;
            float dv1 = (r1 < n) ? g_dinv[r1] : 0.f;
#pragma unroll
            for (int ni = 0; ni < 8; ni++) {
                int col = cb + ni * 8 + t4 * 2;
                if (r0 < n) {
                    float2 o = make_float2(acc[mi][ni][0] * dv0,
                                           acc[mi][ni][1] * dv0);
                    *(float2*)(g_G + (size_t)r0 * 128 + col) = o;
                }
                if (r1 < n) {
                    float2 o = make_float2(acc[mi][ni][2] * dv1,
                                           acc[mi][ni][3] * dv1);
                    *(float2*)(g_G + (size_t)r1 * 128 + col) = o;
                }
            }
        }
    }
}

// ------------------------------------------------------------------
// Fused CSR gather-reduce + finalize (8-deep MLP unroll)
// ------------------------------------------------------------------
__global__ __launch_bounds__(256) void agg_fin_kernel(
    const float* __restrict__ b, int n)
{
    int gid = blockIdx.x * blockDim.x + threadIdx.x;
    int node = gid >> 5;
    int lane = gid & 31;
    if (node >= n) return;

    int beg = g_off[node];
    int end = g_off[node + 1];
    size_t loff = (size_t)lane * 4;

    float4 acc = *(const float4*)(g_G + (size_t)node * 128 + loff);

    int j = beg;
    for (; j + 8 <= end; j += 8) {
        int s0 = g_csr[j + 0], s1 = g_csr[j + 1];
        int s2 = g_csr[j + 2], s3 = g_csr[j + 3];
        int s4 = g_csr[j + 4], s5 = g_csr[j + 5];
        int s6 = g_csr[j + 6], s7 = g_csr[j + 7];
        float4 v0 = *(const float4*)(g_G + (size_t)s0 * 128 + loff);
        float4 v1 = *(const float4*)(g_G + (size_t)s1 * 128 + loff);
        float4 v2 = *(const float4*)(g_G + (size_t)s2 * 128 + loff);
        float4 v3 = *(const float4*)(g_G + (size_t)s3 * 128 + loff);
        float4 v4 = *(const float4*)(g_G + (size_t)s4 * 128 + loff);
        float4 v5 = *(const float4*)(g_G + (size_t)s5 * 128 + loff);
        float4 v6 = *(const float4*)(g_G + (size_t)s6 * 128 + loff);
        float4 v7 = *(const float4*)(g_G + (size_t)s7 * 128 + loff);
        acc.x += (v0.x + v1.x) + (v2.x + v3.x) + ((v4.x + v5.x) + (v6.x + v7.x));
        acc.y += (v0.y + v1.y) + (v2.y + v3.y) + ((v4.y + v5.y) + (v6.y + v7.y));
        acc.z += (v0.z + v1.z) + (v2.z + v3.z) + ((v4.z + v5.z) + (v6.z + v7.z));
        acc.w += (v0.w + v1.w) + (v2.w + v3.w) + ((v4.w + v5.w) + (v6.w + v7.w));
    }
    for (; j + 4 <= end; j += 4) {
        int s0 = g_csr[j + 0], s1 = g_csr[j + 1];
        int s2 = g_csr[j + 2], s3 = g_csr[j + 3];
        float4 v0 = *(const float4*)(g_G + (size_t)s0 * 128 + loff);
        float4 v1 = *(const float4*)(g_G + (size_t)s1 * 128 + loff);
        float4 v2 = *(const float4*)(g_G + (size_t)s2 * 128 + loff);
        float4 v3 = *(const float4*)(g_G + (size_t)s3 * 128 + loff);
        acc.x += (v0.x + v1.x) + (v2.x + v3.x);
        acc.y += (v0.y + v1.y) + (v2.y + v3.y);
        acc.z += (v0.z + v1.z) + (v2.z + v3.z);
        acc.w += (v0.w + v1.w) + (v2.w + v3.w);
    }
    for (; j < end; j++) {
        int s = g_csr[j];
        float4 v = *(const float4*)(g_G + (size_t)s * 128 + loff);
        acc.x += v.x; acc.y += v.y; acc.z += v.z; acc.w += v.w;
    }

    float dv = g_dinv[node];
    float4 bb = *(const float4*)(b + lane * 4);
    float4 o;
    o.x = fmaxf(fmaf(dv, acc.x, bb.x), 0.0f);
    o.y = fmaxf(fmaf(dv, acc.y, bb.y), 0.0f);
    o.z = fmaxf(fmaf(dv, acc.z, bb.z), 0.0f);
    o.w = fmaxf(fmaf(dv, acc.w, bb.w), 0.0f);
    *(float4*)(g_X2 + (size_t)node * 128 + loff) = o;
}

// ------------------------------------------------------------------
// Output GEMM via bf16 split mma: out = X2 @ Wout + bout (K=128, N=40 pad 64)
// Block tile 128x64; warps 4x2, each 32x32 (mi=2, ni=4).
// ------------------------------------------------------------------
__global__ __launch_bounds__(256) void out_gemm_mma_kernel(
    const float* __restrict__ Wout, const float* __restrict__ bout,
    float* __restrict__ out, int n)
{
    extern __shared__ uint32_t smu[];
    int tid = threadIdx.x, w = tid >> 5, lane = tid & 31;
    int g = lane >> 2, t4 = lane & 3;

    // fill Wout hi/lo: B[n][k] = Wout[k][n] for n<40, else 0 (64 rows x 68 u32)
    for (int i = tid; i < 64 * 64; i += 256) {
        int ku = i >> 6, nn2 = i & 63;
        float x0 = (nn2 < 40) ? Wout[(2 * ku) * 40 + nn2] : 0.0f;
        float x1 = (nn2 < 40) ? Wout[(2 * ku + 1) * 40 + nn2] : 0.0f;
        uint32_t lo;
        uint32_t hi = bf16_split_pack(x0, x1, lo);
        smu[OFF_BHI + nn2 * 68 + ku] = hi;
        smu[OFF_BLO + nn2 * 68 + ku] = lo;
    }

    int rb = (w >> 1) * 32;       // warp row base (0,32,64,96)
    int cb = (w & 1) * 32;        // warp col base (0,32)
    int trow = blockIdx.x << 7;

    float4 va[8];
    load_A_regs(g_X2, trow, 0, n, tid, va);
    __syncthreads();   // B fill complete

    float acc[2][4][4];
#pragma unroll
    for (int mi = 0; mi < 2; mi++)
#pragma unroll
        for (int ni = 0; ni < 4; ni++)
#pragma unroll
            for (int j = 0; j < 4; j++) acc[mi][ni][j] = 0.0f;

#pragma unroll
    for (int c = 0; c < 2; c++) {
        store_A_smem(smu, tid, va);
        __syncthreads();
        if (c == 0) load_A_regs(g_X2, trow, 1, n, tid, va);

#pragma unroll
        for (int s = 0; s < 4; s++) {
            int ka = s * 8 + t4;
            int kB = c * 32 + s * 8 + t4;
            uint32_t ah[2][4], al[2][4];
#pragma unroll
            for (int mi = 0; mi < 2; mi++) {
                int r0 = rb + mi * 16 + g;
                const uint32_t* ph = smu + OFF_AHI + r0 * 36 + ka;
                ah[mi][0] = ph[0];
                ah[mi][1] = ph[8 * 36];
                ah[mi][2] = ph[4];
                ah[mi][3] = ph[8 * 36 + 4];
                const uint32_t* pl = smu + OFF_ALO + r0 * 36 + ka;
                al[mi][0] = pl[0];
                al[mi][1] = pl[8 * 36];
                al[mi][2] = pl[4];
                al[mi][3] = pl[8 * 36 + 4];
            }
#pragma unroll
            for (int ni = 0; ni < 4; ni++) {
                int nidx = cb + ni * 8 + g;
                const uint32_t* pbh = smu + OFF_BHI + nidx * 68 + kB;
                const uint32_t* pbl = smu + OFF_BLO + nidx * 68 + kB;
                uint32_t bh[2] = {pbh[0], pbh[4]};
                uint32_t bl[2] = {pbl[0], pbl[4]};
#pragma unroll
                for (int mi = 0; mi < 2; mi++) {
                    mma16(acc[mi][ni], ah[mi], bh);
                    mma16(acc[mi][ni], ah[mi], bl);
                    mma16(acc[mi][ni], al[mi], bh);
                }
            }
        }
        __syncthreads();
    }

    // epilogue: out[row][col] = acc + bout[col], only col < 40
#pragma unroll
    for (int mi = 0; mi < 2; mi++) {
        int r0 = trow + rb + mi * 16 + g;
        int r1 = r0 + 8;
#pragma unroll
        for (int ni = 0; ni < 4; ni++) {
            int col = cb + ni * 8 + t4 * 2;
            if (col < 40) {
                float b0 = __ldg(&bout[col]);
                float b1 = __ldg(&bout[col + 1]);
                if (r0 < n) {
                    float2 o = make_float2(acc[mi][ni][0] + b0,
                                           acc[mi][ni][1] + b1);
                    *(float2*)(out + (size_t)r0 * 40 + col) = o;
                }
                if (r1 < n) {
                    float2 o = make_float2(acc[mi][ni][2] + b0,
                                           acc[mi][ni][3] + b1);
                    *(float2*)(out + (size_t)r1 * 40 + col) = o;
                }
            }
        }
    }
}

// ------------------------------------------------------------------
// launch
// ------------------------------------------------------------------
extern "C" void kernel_launch(void* const* d_in, const int* in_sizes, int n_in,
                              void* d_out, int out_size)
{
    const float* x    = (const float*)d_in[0];
    const int*   ei   = (const int*)d_in[1];
    const float* W1   = (const float*)d_in[2];
    const float* b1   = (const float*)d_in[3];
    const float* W2   = (const float*)d_in[4];
    const float* b2   = (const float*)d_in[5];
    const float* Wout = (const float*)d_in[6];
    const float* bout = (const float*)d_in[7];
    float* out = (float*)d_out;

    int n = in_sizes[0] / 128;
    int e = in_sizes[1] / 2;
    const int* src = ei;
    const int* dst = ei + e;

    cudaFuncSetAttribute(gemm_mma_kernel,
                         cudaFuncAttributeMaxDynamicSharedMemorySize, GEMM_SMEM_B);
    cudaFuncSetAttribute(out_gemm_mma_kernel,
                         cudaFuncAttributeMaxDynamicSharedMemorySize, GEMM_SMEM_B);

    int nb_n = (n + 255) / 256;
    int nb_e = (e + 255) / 256;
    int nb_scan = (n + 1023) / 1024;
    long long agg_threads = (long long)n * 32;
    int nb_agg = (int)((agg_threads + 255) / 256);
    int ntiles = (n + 127) / 128;

    // CSR build (g_cnt zeroed on load and re-zeroed by scan_local each call)
    count_kernel<<<nb_e, 256>>>(dst, e);
    scan_local_kernel<<<nb_scan, 256>>>(n);
    scan_bsums_kernel<<<1, 1024>>>(nb_scan);
    scan_add_kernel<<<nb_n, 256>>>(n, e);
    scatter_kernel<<<nb_e, 256>>>(src, dst, e);

    // layer 1
    gemm_mma_kernel<<<152, 256, GEMM_SMEM_B>>>(x, W1, n, 0);
    agg_fin_kernel<<<nb_agg, 256>>>(b1, n);

    // layer 2
    gemm_mma_kernel<<<152, 256, GEMM_SMEM_B>>>(nullptr, W2, n, 1);
    agg_fin_kernel<<<nb_agg, 256>>>(b2, n);

    // output projection (bf16 split tensor core)
    out_gemm_mma_kernel<<<ntiles, 256, GEMM_SMEM_B>>>(Wout, bout, out, n);
}

// round 17
// speedup vs baseline: 1.4806x; 1.1620x over previous
#include <cuda_runtime.h>
#include <cuda_bf16.h>
#include <cuda_fp16.h>
#include <cstdint>

#define NN 100000
#define EE 1600000

// ---- device scratch ----
__device__ int      g_cnt[NN];     // zero-init by CUDA; re-zeroed each call in scan_local
__device__ int      g_off[NN + 1];
__device__ int      g_cur[NN];
__device__ int      g_bsum[1024];
__device__ int      g_csr[EE];
__device__ float    g_dinv[NN];
__device__ uint32_t g_Gh[NN * 64]; // messages in fp16: 64 half2 per row (256 B)
__device__ float    g_X2[NN * 128];

// ------------------------------------------------------------------
// CSR build
// ------------------------------------------------------------------
__global__ void count_kernel(const int* __restrict__ dst, int e) {
    int i = blockIdx.x * blockDim.x + threadIdx.x;
    if (i < e) atomicAdd(&g_cnt[dst[i]], 1);
}
__global__ __launch_bounds__(256) void scan_local_kernel(int n) {
    __shared__ int ssum[256];
    int t = threadIdx.x;
    int base = blockIdx.x * 1024 + t * 4;
    int c0 = (base + 0 < n) ? g_cnt[base + 0] : 0;
    int c1 = (base + 1 < n) ? g_cnt[base + 1] : 0;
    int c2 = (base + 2 < n) ? g_cnt[base + 2] : 0;
    int c3 = (base + 3 < n) ? g_cnt[base + 3] : 0;
    if (base + 0 < n) { g_dinv[base + 0] = rsqrtf((float)c0 + 1.0f); g_cnt[base + 0] = 0; }
    if (base + 1 < n) { g_dinv[base + 1] = rsqrtf((float)c1 + 1.0f); g_cnt[base + 1] = 0; }
    if (base + 2 < n) { g_dinv[base + 2] = rsqrtf((float)c2 + 1.0f); g_cnt[base + 2] = 0; }
    if (base + 3 < n) { g_dinv[base + 3] = rsqrtf((float)c3 + 1.0f); g_cnt[base + 3] = 0; }
    int tsum = c0 + c1 + c2 + c3;
    ssum[t] = tsum;
    __syncthreads();
    for (int off = 1; off < 256; off <<= 1) {
        int v = (t >= off) ? ssum[t - off] : 0;
        __syncthreads();
        ssum[t] += v;
        __syncthreads();
    }
    int excl = ssum[t] - tsum;
    if (base + 0 < n) g_off[base + 0] = excl;
    if (base + 1 < n) g_off[base + 1] = excl + c0;
    if (base + 2 < n) g_off[base + 2] = excl + c0 + c1;
    if (base + 3 < n) g_off[base + 3] = excl + c0 + c1 + c2;
    if (t == 255) g_bsum[blockIdx.x] = ssum[255];
}
__global__ __launch_bounds__(1024) void scan_bsums_kernel(int nb) {
    __shared__ int s[1024];
    int t = threadIdx.x;
    int v = (t < nb) ? g_bsum[t] : 0;
    s[t] = v;
    __syncthreads();
    for (int off = 1; off < 1024; off <<= 1) {
        int u = (t >= off) ? s[t - off] : 0;
        __syncthreads();
        s[t] += u;
        __syncthreads();
    }
    if (t < nb) g_bsum[t] = s[t] - v;
}
__global__ void scan_add_kernel(int n, int e) {
    int i = blockIdx.x * blockDim.x + threadIdx.x;
    if (i < n) {
        int v = g_off[i] + g_bsum[i >> 10];
        g_off[i] = v;
        g_cur[i] = v;
    }
    if (i == 0) g_off[n] = e;
}
__global__ void scatter_kernel(const int* __restrict__ src,
                               const int* __restrict__ dst, int e) {
    int i = blockIdx.x * blockDim.x + threadIdx.x;
    if (i < e) {
        int pos = atomicAdd(&g_cur[dst[i]], 1);
        g_csr[pos] = src[i];
    }
}

// ------------------------------------------------------------------
// bf16 3-term split GEMM via mma.sync.m16n8k16 + ldmatrix (sm_80 PTX)
// ------------------------------------------------------------------
__device__ __forceinline__ void mma16(float* d, const uint32_t* a, const uint32_t* b) {
    asm volatile(
        "mma.sync.aligned.m16n8k16.row.col.f32.bf16.bf16.f32 "
        "{%0,%1,%2,%3}, {%4,%5,%6,%7}, {%8,%9}, {%0,%1,%2,%3};"
        : "+f"(d[0]), "+f"(d[1]), "+f"(d[2]), "+f"(d[3])
        : "r"(a[0]), "r"(a[1]), "r"(a[2]), "r"(a[3]), "r"(b[0]), "r"(b[1]));
}

#define LDMX4(d, addr) \
    asm volatile("ldmatrix.sync.aligned.m8n8.x4.shared.b16 {%0,%1,%2,%3}, [%4];" \
        : "=r"((d)[0]), "=r"((d)[1]), "=r"((d)[2]), "=r"((d)[3]) : "r"(addr))

// split x into bf16 hi + bf16 lo residual; pack (x0,x1) pairs (x0 in low half)
__device__ __forceinline__ uint32_t bf16_split_pack(float x0, float x1, uint32_t& lopack) {
    __nv_bfloat16 h0 = __float2bfloat16(x0);
    __nv_bfloat16 h1 = __float2bfloat16(x1);
    float r0 = x0 - __bfloat162float(h0);
    float r1 = x1 - __bfloat162float(h1);
    __nv_bfloat16 l0 = __float2bfloat16(r0);
    __nv_bfloat16 l1 = __float2bfloat16(r1);
    lopack = ((uint32_t)__bfloat16_as_ushort(l1) << 16) | (uint32_t)__bfloat16_as_ushort(l0);
    return ((uint32_t)__bfloat16_as_ushort(h1) << 16) | (uint32_t)__bfloat16_as_ushort(h0);
}

// smem (u32 units): Bhi[128 rows x 68], Blo, Ahi[128 x 36], Alo
#define OFF_BHI 0
#define OFF_BLO 8704
#define OFF_AHI 17408
#define OFF_ALO 22016
#define GEMM_SMEM_U 26624
#define GEMM_SMEM_B (GEMM_SMEM_U * 4)   // 106496 B

// load one A chunk (K=64 cols starting at c*64) into 8 float4 regs
__device__ __forceinline__ void load_A_regs(
    const float* __restrict__ X, int trow, int c, int n, int tid, float4* va)
{
#pragma unroll
    for (int j = 0; j < 8; j++) {
        int i4 = tid + j * 256;
        int m = i4 >> 4, q = i4 & 15;
        int row = trow + m;
        va[j] = make_float4(0.f, 0.f, 0.f, 0.f);
        if (row < n)
            va[j] = *(const float4*)(X + (size_t)row * 128 + c * 64 + q * 4);
    }
}

// convert regs -> bf16 hi/lo pairs and store to smem A (chunk-local 32 u32 + pad)
__device__ __forceinline__ void store_A_smem(uint32_t* smu, int tid, const float4* va)
{
#pragma unroll
    for (int j = 0; j < 8; j++) {
        int i4 = tid + j * 256;
        int m = i4 >> 4, q = i4 & 15;
        float4 v = va[j];
        uint32_t lo0, lo1;
        uint32_t hi0 = bf16_split_pack(v.x, v.y, lo0);
        uint32_t hi1 = bf16_split_pack(v.z, v.w, lo1);
        int base = m * 36 + 2 * q;
        smu[OFF_AHI + base]     = hi0;
        smu[OFF_AHI + base + 1] = hi1;
        smu[OFF_ALO + base]     = lo0;
        smu[OFF_ALO + base + 1] = lo1;
    }
}

// G = fp16(dinv[row] * (X @ W)); persistent; M-tile 128, N=128, K=128
__global__ __launch_bounds__(256) void gemm_mma_kernel(
    const float* __restrict__ Xext, const float* __restrict__ W,
    int n, int use_x2)
{
    extern __shared__ uint32_t smu[];
    const float* X = use_x2 ? g_X2 : Xext;
    int tid = threadIdx.x, w = tid >> 5, lane = tid & 31;
    int g = lane >> 2, t4 = lane & 3;

    // fill W hi/lo once: B[n][k] = W[k][n], bf16 pairs, row stride 68 u32
    for (int i = tid; i < 64 * 128; i += 256) {
        int ku = i >> 7, nn2 = i & 127;
        float x0 = W[(2 * ku) * 128 + nn2];
        float x1 = W[(2 * ku + 1) * 128 + nn2];
        uint32_t lo;
        uint32_t hi = bf16_split_pack(x0, x1, lo);
        smu[OFF_BHI + nn2 * 68 + ku] = hi;
        smu[OFF_BLO + nn2 * 68 + ku] = lo;
    }

    int rb = (w >> 1) * 32;       // warp row base (0,32,64,96)
    int cb = (w & 1) * 64;        // warp col base (0,64)
    int ntiles = (n + 127) >> 7;
    int stride = gridDim.x;

    // ldmatrix per-lane base addresses
    uint32_t sbase = (uint32_t)__cvta_generic_to_shared(smu);
    uint32_t a_row = (uint32_t)(rb + (lane & 15));
    uint32_t a_base_hi = sbase + (OFF_AHI + a_row * 36 + ((lane >> 4) << 2)) * 4;
    uint32_t a_base_lo = a_base_hi + (OFF_ALO - OFF_AHI) * 4;
    uint32_t grp = (uint32_t)(lane >> 3);
    uint32_t b_row = (uint32_t)(cb + (lane & 7) + ((grp >> 1) << 3));
    uint32_t b_base_hi = sbase + (OFF_BHI + b_row * 68 + ((grp & 1) << 2)) * 4;
    uint32_t b_base_lo = b_base_hi + (OFF_BLO - OFF_BHI) * 4;

    float4 va[8];
    int t = blockIdx.x;
    if (t < ntiles) load_A_regs(X, t << 7, 0, n, tid, va);
    __syncthreads();   // W fill complete

    for (; t < ntiles; t += stride) {
        int trow = t << 7;

        float acc[2][8][4];
#pragma unroll
        for (int mi = 0; mi < 2; mi++)
#pragma unroll
            for (int ni = 0; ni < 8; ni++)
#pragma unroll
                for (int j = 0; j < 4; j++) acc[mi][ni][j] = 0.0f;

#pragma unroll
        for (int c = 0; c < 2; c++) {
            store_A_smem(smu, tid, va);
            __syncthreads();

            int tn = (c == 0) ? t : t + stride;
            int cn = c ^ 1;
            if (tn < ntiles) load_A_regs(X, tn << 7, cn, n, tid, va);

#pragma unroll
            for (int s = 0; s < 4; s++) {
                uint32_t aoff = (uint32_t)(s * 8) * 4;
                uint32_t boff = (uint32_t)(c * 32 + s * 8) * 4;
                uint32_t ah[2][4], al[2][4];
#pragma unroll
                for (int mi = 0; mi < 2; mi++) {
                    LDMX4(ah[mi], a_base_hi + (uint32_t)(mi * 576) * 4 + aoff);
                    LDMX4(al[mi], a_base_lo + (uint32_t)(mi * 576) * 4 + aoff);
                }
#pragma unroll
                for (int nj = 0; nj < 4; nj++) {
                    uint32_t bh2[4], bl2[4];
                    LDMX4(bh2, b_base_hi + (uint32_t)(nj * 1088) * 4 + boff);
                    LDMX4(bl2, b_base_lo + (uint32_t)(nj * 1088) * 4 + boff);
#pragma unroll
                    for (int p = 0; p < 2; p++) {
                        int ni = 2 * nj + p;
#pragma unroll
                        for (int mi = 0; mi < 2; mi++) {
                            mma16(acc[mi][ni], ah[mi], bh2 + 2 * p);
                            mma16(acc[mi][ni], ah[mi], bl2 + 2 * p);
                            mma16(acc[mi][ni], al[mi], bh2 + 2 * p);
                        }
                    }
                }
            }
            __syncthreads();
        }

        // epilogue: fp16(acc * dinv) -> g_Gh (one half2 per col pair)
#pragma unroll
        for (int mi = 0; mi < 2; mi++) {
            int r0 = trow + rb + mi * 16 + g;
            int r1 = r0 + 8;
            float dv0 = (r0 < n) ? g_dinv[r0] : 0.f;
            float dv1 = (r1 < n) ? g_dinv[r1] : 0.f;
#pragma unroll
            for (int ni = 0; ni < 8; ni++) {
                int colh = (cb >> 1) + ni * 4 + t4;   // half2 index within row
                if (r0 < n) {
                    __half2 h = __floats2half2_rn(acc[mi][ni][0] * dv0,
                                                  acc[mi][ni][1] * dv0);
                    g_Gh[(size_t)r0 * 64 + colh] = *(uint32_t*)&h;
                }
                if (r1 < n) {
                    __half2 h = __floats2half2_rn(acc[mi][ni][2] * dv1,
                                                  acc[mi][ni][3] * dv1);
                    g_Gh[(size_t)r1 * 64 + colh] = *(uint32_t*)&h;
                }
            }
        }
    }
}

// ------------------------------------------------------------------
// Fused CSR gather-reduce + finalize (fp16 messages, 8-deep MLP)
// ------------------------------------------------------------------
__device__ __forceinline__ void acc_row(float4& acc, uint2 u) {
    float2 a = __half22float2(*(__half2*)&u.x);
    float2 b = __half22float2(*(__half2*)&u.y);
    acc.x += a.x; acc.y += a.y; acc.z += b.x; acc.w += b.y;
}

__global__ __launch_bounds__(256) void agg_fin_kernel(
    const float* __restrict__ b, int n)
{
    int gid = blockIdx.x * blockDim.x + threadIdx.x;
    int node = gid >> 5;
    int lane = gid & 31;
    if (node >= n) return;

    int beg = g_off[node];
    int end = g_off[node + 1];
    size_t loff = (size_t)lane * 2;   // u32 (half2) offset within 64-u32 row

    float4 acc = make_float4(0.f, 0.f, 0.f, 0.f);
    acc_row(acc, *(const uint2*)(g_Gh + (size_t)node * 64 + loff));  // self

    int j = beg;
    for (; j + 8 <= end; j += 8) {
        int s0 = g_csr[j + 0], s1 = g_csr[j + 1];
        int s2 = g_csr[j + 2], s3 = g_csr[j + 3];
        int s4 = g_csr[j + 4], s5 = g_csr[j + 5];
        int s6 = g_csr[j + 6], s7 = g_csr[j + 7];
        uint2 u0 = *(const uint2*)(g_Gh + (size_t)s0 * 64 + loff);
        uint2 u1 = *(const uint2*)(g_Gh + (size_t)s1 * 64 + loff);
        uint2 u2 = *(const uint2*)(g_Gh + (size_t)s2 * 64 + loff);
        uint2 u3 = *(const uint2*)(g_Gh + (size_t)s3 * 64 + loff);
        uint2 u4 = *(const uint2*)(g_Gh + (size_t)s4 * 64 + loff);
        uint2 u5 = *(const uint2*)(g_Gh + (size_t)s5 * 64 + loff);
        uint2 u6 = *(const uint2*)(g_Gh + (size_t)s6 * 64 + loff);
        uint2 u7 = *(const uint2*)(g_Gh + (size_t)s7 * 64 + loff);
        acc_row(acc, u0); acc_row(acc, u1); acc_row(acc, u2); acc_row(acc, u3);
        acc_row(acc, u4); acc_row(acc, u5); acc_row(acc, u6); acc_row(acc, u7);
    }
    for (; j + 4 <= end; j += 4) {
        int s0 = g_csr[j + 0], s1 = g_csr[j + 1];
        int s2 = g_csr[j + 2], s3 = g_csr[j + 3];
        uint2 u0 = *(const uint2*)(g_Gh + (size_t)s0 * 64 + loff);
        uint2 u1 = *(const uint2*)(g_Gh + (size_t)s1 * 64 + loff);
        uint2 u2 = *(const uint2*)(g_Gh + (size_t)s2 * 64 + loff);
        uint2 u3 = *(const uint2*)(g_Gh + (size_t)s3 * 64 + loff);
        acc_row(acc, u0); acc_row(acc, u1); acc_row(acc, u2); acc_row(acc, u3);
    }
    for (; j < end; j++) {
        int s = g_csr[j];
        acc_row(acc, *(const uint2*)(g_Gh + (size_t)s * 64 + loff));
    }

    float dv = g_dinv[node];
    float4 bb = *(const float4*)(b + lane * 4);
    float4 o;
    o.x = fmaxf(fmaf(dv, acc.x, bb.x), 0.0f);
    o.y = fmaxf(fmaf(dv, acc.y, bb.y), 0.0f);
    o.z = fmaxf(fmaf(dv, acc.z, bb.z), 0.0f);
    o.w = fmaxf(fmaf(dv, acc.w, bb.w), 0.0f);
    *(float4*)(g_X2 + (size_t)node * 128 + (size_t)lane * 4) = o;
}

// ------------------------------------------------------------------
// Output GEMM via bf16 split mma: out = X2 @ Wout + bout (K=128, N=40 pad 64)
// ------------------------------------------------------------------
__global__ __launch_bounds__(256) void out_gemm_mma_kernel(
    const float* __restrict__ Wout, const float* __restrict__ bout,
    float* __restrict__ out, int n)
{
    extern __shared__ uint32_t smu[];
    int tid = threadIdx.x, w = tid >> 5, lane = tid & 31;
    int g = lane >> 2, t4 = lane & 3;

    for (int i = tid; i < 64 * 64; i += 256) {
        int ku = i >> 6, nn2 = i & 63;
        float x0 = (nn2 < 40) ? Wout[(2 * ku) * 40 + nn2] : 0.0f;
        float x1 = (nn2 < 40) ? Wout[(2 * ku + 1) * 40 + nn2] : 0.0f;
        uint32_t lo;
        uint32_t hi = bf16_split_pack(x0, x1, lo);
        smu[OFF_BHI + nn2 * 68 + ku] = hi;
        smu[OFF_BLO + nn2 * 68 + ku] = lo;
    }

    int rb = (w >> 1) * 32;       // warp row base (0,32,64,96)
    int cb = (w & 1) * 32;        // warp col base (0,32)
    int trow = blockIdx.x << 7;

    float4 va[8];
    load_A_regs(g_X2, trow, 0, n, tid, va);
    __syncthreads();

    float acc[2][4][4];
#pragma unroll
    for (int mi = 0; mi < 2; mi++)
#pragma unroll
        for (int ni = 0; ni < 4; ni++)
#pragma unroll
            for (int j = 0; j < 4; j++) acc[mi][ni][j] = 0.0f;

#pragma unroll
    for (int c = 0; c < 2; c++) {
        store_A_smem(smu, tid, va);
        __syncthreads();
        if (c == 0) load_A_regs(g_X2, trow, 1, n, tid, va);

#pragma unroll
        for (int s = 0; s < 4; s++) {
            int ka = s * 8 + t4;
            int kB = c * 32 + s * 8 + t4;
            uint32_t ah[2][4], al[2][4];
#pragma unroll
            for (int mi = 0; mi < 2; mi++) {
                int r0 = rb + mi * 16 + g;
                const uint32_t* ph = smu + OFF_AHI + r0 * 36 + ka;
                ah[mi][0] = ph[0];
                ah[mi][1] = ph[8 * 36];
                ah[mi][2] = ph[4];
                ah[mi][3] = ph[8 * 36 + 4];
                const uint32_t* pl = smu + OFF_ALO + r0 * 36 + ka;
                al[mi][0] = pl[0];
                al[mi][1] = pl[8 * 36];
                al[mi][2] = pl[4];
                al[mi][3] = pl[8 * 36 + 4];
            }
#pragma unroll
            for (int ni = 0; ni < 4; ni++) {
                int nidx = cb + ni * 8 + g;
                const uint32_t* pbh = smu + OFF_BHI + nidx * 68 + kB;
                const uint32_t* pbl = smu + OFF_BLO + nidx * 68 + kB;
                uint32_t bh[2] = {pbh[0], pbh[4]};
                uint32_t bl[2] = {pbl[0], pbl[4]};
#pragma unroll
                for (int mi = 0; mi < 2; mi++) {
                    mma16(acc[mi][ni], ah[mi], bh);
                    mma16(acc[mi][ni], ah[mi], bl);
                    mma16(acc[mi][ni], al[mi], bh);
                }
            }
        }
        __syncthreads();
    }

#pragma unroll
    for (int mi = 0; mi < 2; mi++) {
        int r0 = trow + rb + mi * 16 + g;
        int r1 = r0 + 8;
#pragma unroll
        for (int ni = 0; ni < 4; ni++) {
            int col = cb + ni * 8 + t4 * 2;
            if (col < 40) {
                float b0 = __ldg(&bout[col]);
                float b1 = __ldg(&bout[col + 1]);
                if (r0 < n) {
                    float2 o = make_float2(acc[mi][ni][0] + b0,
                                           acc[mi][ni][1] + b1);
                    *(float2*)(out + (size_t)r0 * 40 + col) = o;
                }
                if (r1 < n) {
                    float2 o = make_float2(acc[mi][ni][2] + b0,
                                           acc[mi][ni][3] + b1);
                    *(float2*)(out + (size_t)r1 * 40 + col) = o;
                }
            }
        }
    }
}

// ------------------------------------------------------------------
// launch
// ------------------------------------------------------------------
extern "C" void kernel_launch(void* const* d_in, const int* in_sizes, int n_in,
                              void* d_out, int out_size)
{
    const float* x    = (const float*)d_in[0];
    const int*   ei   = (const int*)d_in[1];
    const float* W1   = (const float*)d_in[2];
    const float* b1   = (const float*)d_in[3];
    const float* W2   = (const float*)d_in[4];
    const float* b2   = (const float*)d_in[5];
    const float* Wout = (const float*)d_in[6];
    const float* bout = (const float*)d_in[7];
    float* out = (float*)d_out;

    int n = in_sizes[0] / 128;
    int e = in_sizes[1] / 2;
    const int* src = ei;
    const int* dst = ei + e;

    cudaFuncSetAttribute(gemm_mma_kernel,
                         cudaFuncAttributeMaxDynamicSharedMemorySize, GEMM_SMEM_B);
    cudaFuncSetAttribute(out_gemm_mma_kernel,
                         cudaFuncAttributeMaxDynamicSharedMemorySize, GEMM_SMEM_B);

    int nb_n = (n + 255) / 256;
    int nb_e = (e + 255) / 256;
    int nb_scan = (n + 1023) / 1024;
    long long agg_threads = (long long)n * 32;
    int nb_agg = (int)((agg_threads + 255) / 256);
    int ntiles = (n + 127) / 128;

    // CSR build (g_cnt zeroed on load and re-zeroed by scan_local each call)
    count_kernel<<<nb_e, 256>>>(dst, e);
    scan_local_kernel<<<nb_scan, 256>>>(n);
    scan_bsums_kernel<<<1, 1024>>>(nb_scan);
    scan_add_kernel<<<nb_n, 256>>>(n, e);
    scatter_kernel<<<nb_e, 256>>>(src, dst, e);

    // layer 1
    gemm_mma_kernel<<<152, 256, GEMM_SMEM_B>>>(x, W1, n, 0);
    agg_fin_kernel<<<nb_agg, 256>>>(b1, n);

    // layer 2
    gemm_mma_kernel<<<152, 256, GEMM_SMEM_B>>>(nullptr, W2, n, 1);
    agg_fin_kernel<<<nb_agg, 256>>>(b2, n);

    // output projection (bf16 split tensor core)
    out_gemm_mma_kernel<<<ntiles, 256, GEMM_SMEM_B>>>(Wout, bout, out, n);
}